// round 9
// baseline (speedup 1.0000x reference)
#include <cuda_runtime.h>
#include <cuda_bf16.h>

// Problem constants
#define N_DET   20000
#define IN_DIM  151
#define HID_DIM 256
#define OUT_DIM 128
#define IN_P    80       // padded k-pairs for IN_DIM (76 real, 4 zero) -> 5 steps of 16
#define HID_P   128      // k-pairs for HID_DIM -> 8 steps of 16

// Scratch (allocation forbidden -> __device__ globals)
__device__ __align__(16) float    g_S[N_DET * OUT_DIM];
__device__ __align__(16) float    g_O[N_DET * OUT_DIM];
__device__ __align__(16) unsigned g_Xp_hi[N_DET * IN_P];
__device__ __align__(16) unsigned g_Xp_lo[N_DET * IN_P];
__device__ __align__(16) unsigned g_W1p_hi[2][IN_P * HID_DIM];
__device__ __align__(16) unsigned g_W1p_lo[2][IN_P * HID_DIM];
__device__ __align__(16) unsigned g_W2p_hi[2][HID_P * OUT_DIM];
__device__ __align__(16) unsigned g_W2p_lo[2][HID_P * OUT_DIM];
__device__ int g_idx64;

// ---------------------------------------------------------------------------
__global__ void probe_dtype(const long long* __restrict__ e)
{
    bool ok64 = true;
    for (int i = 0; i < 48; i++) {
        long long v = e[i];
        if (v < 0 || v >= N_DET) ok64 = false;
    }
    g_idx64 = ok64 ? 1 : 0;
}

// ---------------------------------------------------------------------------
// bf16 split helpers
// ---------------------------------------------------------------------------
__device__ __forceinline__ void split_bf16(float v, unsigned short& hi, unsigned short& lo)
{
    __nv_bfloat16 h = __float2bfloat16(v);
    __nv_bfloat16 l = __float2bfloat16(v - __bfloat162float(h));
    hi = __bfloat16_as_ushort(h);
    lo = __bfloat16_as_ushort(l);
}
__device__ __forceinline__ unsigned pack2(unsigned short a, unsigned short b)
{
    return (unsigned)a | ((unsigned)b << 16);
}
__device__ __forceinline__ void split_pair(float v0, float v1, unsigned& hi, unsigned& lo)
{
    unsigned short h0, l0, h1, l1;
    split_bf16(v0, h0, l0);
    split_bf16(v1, h1, l1);
    hi = pack2(h0, h1);
    lo = pack2(l0, l1);
}

// D += A(16x16,row) * B(16x8,col); bf16 inputs, fp32 accum.
__device__ __forceinline__ void mma_bf16(float* d, const unsigned* a, const unsigned* b)
{
    asm("mma.sync.aligned.m16n8k16.row.col.f32.bf16.bf16.f32 "
        "{%0,%1,%2,%3}, {%4,%5,%6,%7}, {%8,%9}, {%0,%1,%2,%3};"
        : "+f"(d[0]), "+f"(d[1]), "+f"(d[2]), "+f"(d[3])
        : "r"(a[0]), "r"(a[1]), "r"(a[2]), "r"(a[3]), "r"(b[0]), "r"(b[1]));
}

// cp.async 16B global->shared
__device__ __forceinline__ void cp16(unsigned* dst, const unsigned* src)
{
    unsigned d = (unsigned)__cvta_generic_to_shared(dst);
    asm volatile("cp.async.cg.shared.global [%0], [%1], 16;" :: "r"(d), "l"(src));
}
__device__ __forceinline__ void cp_wait_all()
{
    asm volatile("cp.async.wait_all;" ::: "memory");
}

// ---------------------------------------------------------------------------
// Prep: split X into packed bf16 k-pairs (padded to IN_P pairs per row).
// ---------------------------------------------------------------------------
__global__ void prep_X(const float* __restrict__ X)
{
    int idx = blockIdx.x * blockDim.x + threadIdx.x;
    if (idx >= N_DET * IN_P) return;
    int row = idx / IN_P, j = idx - row * IN_P;
    float v0 = (2 * j     < IN_DIM) ? X[(size_t)row * IN_DIM + 2 * j]     : 0.f;
    float v1 = (2 * j + 1 < IN_DIM) ? X[(size_t)row * IN_DIM + 2 * j + 1] : 0.f;
    unsigned hi, lo;
    split_pair(v0, v1, hi, lo);
    g_Xp_hi[idx] = hi;
    g_Xp_lo[idx] = lo;
}

// Prep: split both nets' W1 (IN_P x HID_DIM pairs) and W2 (HID_P x OUT_DIM).
__global__ void prep_W(const float* __restrict__ Ws_w1, const float* __restrict__ Wo_w1,
                       const float* __restrict__ Ws_w2, const float* __restrict__ Wo_w2)
{
    int idx = blockIdx.x * blockDim.x + threadIdx.x;
    const int W1TOT = 2 * IN_P * HID_DIM;    // 40960
    const int W2TOT = 2 * HID_P * OUT_DIM;   // 32768
    if (idx < W1TOT) {
        int net = idx / (IN_P * HID_DIM);
        int r = idx - net * (IN_P * HID_DIM);
        int j = r / HID_DIM, n = r - j * HID_DIM;
        const float* W = net ? Wo_w1 : Ws_w1;
        float v0 = (2 * j     < IN_DIM) ? W[(size_t)(2 * j)     * HID_DIM + n] : 0.f;
        float v1 = (2 * j + 1 < IN_DIM) ? W[(size_t)(2 * j + 1) * HID_DIM + n] : 0.f;
        unsigned hi, lo;
        split_pair(v0, v1, hi, lo);
        g_W1p_hi[net][r] = hi;
        g_W1p_lo[net][r] = lo;
    } else if (idx < W1TOT + W2TOT) {
        int k = idx - W1TOT;
        int net = k / (HID_P * OUT_DIM);
        int r = k - net * (HID_P * OUT_DIM);
        int j = r / OUT_DIM, n = r - j * OUT_DIM;
        const float* W = net ? Wo_w2 : Ws_w2;
        float v0 = W[(size_t)(2 * j)     * OUT_DIM + n];
        float v1 = W[(size_t)(2 * j + 1) * OUT_DIM + n];
        unsigned hi, lo;
        split_pair(v0, v1, hi, lo);
        g_W2p_hi[net][r] = hi;
        g_W2p_lo[net][r] = lo;
    }
}

// ---------------------------------------------------------------------------
// Fused MLP v2: per CTA = 64 rows x one net. 256 threads (8 warps, 2x4).
// Phase 1: H = relu(X@W1+b1) (64x256) kept split-packed in smem.
// Phase 2: T = H@W2+b2 -> g_S/g_O.
// 111.1 KB smem -> 2 CTAs/SM; stages via cp.async; 16 k-pairs per barrier.
// ---------------------------------------------------------------------------
// smem word layout
#define HS_STRIDE 66
#define SA_STRIDE 20
#define SB1_STRIDE 260
#define SB2_STRIDE 132
#define HS_WORDS  (HID_P * HS_STRIDE)        // 8448 per half
#define SA_WORDS  (64 * SA_STRIDE)           // 1280 per half
#define SB_WORDS  (16 * SB1_STRIDE)          // 4160 per half
#define SMEM_WORDS (2 * HS_WORDS + 2 * SA_WORDS + 2 * SB_WORDS)   // 27776 = 111104 B

__global__ __launch_bounds__(256, 2)
void fused_mlp(const float* __restrict__ b1s, const float* __restrict__ b1o,
               const float* __restrict__ b2s, const float* __restrict__ b2o)
{
    extern __shared__ unsigned sm[];
    unsigned* Hs_hi = sm;                    // [HID_P][66]   (k-pair major)
    unsigned* Hs_lo = Hs_hi + HS_WORDS;
    unsigned* SA_hi = Hs_lo + HS_WORDS;      // [64][20]      (row major, 16 pairs + pad)
    unsigned* SA_lo = SA_hi + SA_WORDS;
    unsigned* SB_hi = SA_lo + SA_WORDS;      // [16][260] p1 / [16][132] p2
    unsigned* SB_lo = SB_hi + SB_WORDS;

    const int tid  = threadIdx.x;
    const int warp = tid >> 5, lane = tid & 31;
    const int g = lane >> 2, t = lane & 3;
    const int wm = warp >> 2, wn = warp & 3;   // 2 x 4 warp grid
    const int row0 = blockIdx.x * 64;
    const int net  = blockIdx.y;

    const unsigned* W1h = g_W1p_hi[net];
    const unsigned* W1l = g_W1p_lo[net];
    const unsigned* W2h = g_W2p_hi[net];
    const unsigned* W2l = g_W2p_lo[net];
    const float* b1 = net ? b1o : b1s;
    const float* b2 = net ? b2o : b2s;
    float* out = net ? g_O : g_S;

    // ---------------- Phase 1: H = relu(X @ W1 + b1) ----------------
    float acc[2][8][4];
#pragma unroll
    for (int mi = 0; mi < 2; mi++)
#pragma unroll
        for (int ni = 0; ni < 8; ni++)
#pragma unroll
            for (int r = 0; r < 4; r++) acc[mi][ni][r] = 0.f;

    for (int s = 0; s < IN_P / 16; s++) {      // 5 steps of 16 pairs
        // SA stage: 64 rows x 16 pairs; one 16B chunk per thread per half
        {
            int row = tid >> 2, c = tid & 3;
            int grow = row0 + row;
            if (grow >= N_DET) grow = 0;       // clamp: junk rows discarded in epilogue
            size_t off = (size_t)grow * IN_P + s * 16 + c * 4;
            cp16(&SA_hi[row * SA_STRIDE + c * 4], &g_Xp_hi[off]);
            cp16(&SA_lo[row * SA_STRIDE + c * 4], &g_Xp_lo[off]);
        }
        // SB stage: 16 k2-rows x 256 n; 4 chunks per thread per half
#pragma unroll
        for (int i = 0; i < 4; i++) {
            int idx = tid + i * 256;
            int k2 = idx >> 6, c = idx & 63;
            size_t off = (size_t)(s * 16 + k2) * HID_DIM + c * 4;
            cp16(&SB_hi[k2 * SB1_STRIDE + c * 4], &W1h[off]);
            cp16(&SB_lo[k2 * SB1_STRIDE + c * 4], &W1l[off]);
        }
        cp_wait_all();
        __syncthreads();

#pragma unroll
        for (int kk = 0; kk < 2; kk++) {
            int ko = kk * 8;
            unsigned ah[2][4], al[2][4];
#pragma unroll
            for (int mi = 0; mi < 2; mi++) {
                int mr = wm * 32 + mi * 16;
                ah[mi][0] = SA_hi[(mr + g)     * SA_STRIDE + ko + t];
                ah[mi][1] = SA_hi[(mr + g + 8) * SA_STRIDE + ko + t];
                ah[mi][2] = SA_hi[(mr + g)     * SA_STRIDE + ko + t + 4];
                ah[mi][3] = SA_hi[(mr + g + 8) * SA_STRIDE + ko + t + 4];
                al[mi][0] = SA_lo[(mr + g)     * SA_STRIDE + ko + t];
                al[mi][1] = SA_lo[(mr + g + 8) * SA_STRIDE + ko + t];
                al[mi][2] = SA_lo[(mr + g)     * SA_STRIDE + ko + t + 4];
                al[mi][3] = SA_lo[(mr + g + 8) * SA_STRIDE + ko + t + 4];
            }
#pragma unroll
            for (int ni = 0; ni < 8; ni++) {
                int nc = wn * 64 + ni * 8;
                unsigned bh[2], bl[2];
                bh[0] = SB_hi[(ko + t)     * SB1_STRIDE + nc + g];
                bh[1] = SB_hi[(ko + t + 4) * SB1_STRIDE + nc + g];
                bl[0] = SB_lo[(ko + t)     * SB1_STRIDE + nc + g];
                bl[1] = SB_lo[(ko + t + 4) * SB1_STRIDE + nc + g];
#pragma unroll
                for (int mi = 0; mi < 2; mi++) {
                    mma_bf16(acc[mi][ni], ah[mi], bh);
                    mma_bf16(acc[mi][ni], ah[mi], bl);
                    mma_bf16(acc[mi][ni], al[mi], bh);
                }
            }
        }
        __syncthreads();
    }

    // H epilogue: bias + relu, split-pack into Hs [k2][m]
#pragma unroll
    for (int mi = 0; mi < 2; mi++) {
        int r0 = wm * 32 + mi * 16 + g;
        int r1 = r0 + 8;
#pragma unroll
        for (int ni = 0; ni < 8; ni++) {
            int c0 = wn * 64 + ni * 8 + 2 * t;
            float bb0 = __ldg(&b1[c0]), bb1 = __ldg(&b1[c0 + 1]);
            float v00 = fmaxf(acc[mi][ni][0] + bb0, 0.f);
            float v01 = fmaxf(acc[mi][ni][1] + bb1, 0.f);
            float v10 = fmaxf(acc[mi][ni][2] + bb0, 0.f);
            float v11 = fmaxf(acc[mi][ni][3] + bb1, 0.f);
            int k2 = c0 >> 1;
            unsigned hi, lo;
            split_pair(v00, v01, hi, lo);
            Hs_hi[k2 * HS_STRIDE + r0] = hi;
            Hs_lo[k2 * HS_STRIDE + r0] = lo;
            split_pair(v10, v11, hi, lo);
            Hs_hi[k2 * HS_STRIDE + r1] = hi;
            Hs_lo[k2 * HS_STRIDE + r1] = lo;
        }
    }
    __syncthreads();

    // ---------------- Phase 2: T = H @ W2 + b2 ----------------
    float acc2[2][4][4];
#pragma unroll
    for (int mi = 0; mi < 2; mi++)
#pragma unroll
        for (int ni = 0; ni < 4; ni++)
#pragma unroll
            for (int r = 0; r < 4; r++) acc2[mi][ni][r] = 0.f;

    for (int s = 0; s < HID_P / 16; s++) {     // 8 steps of 16 pairs
        // B2 stage: 16 k2-rows x 128 n; 2 chunks per thread per half
#pragma unroll
        for (int i = 0; i < 2; i++) {
            int idx = tid + i * 256;
            int k2 = idx >> 5, c = idx & 31;
            size_t off = (size_t)(s * 16 + k2) * OUT_DIM + c * 4;
            cp16(&SB_hi[k2 * SB2_STRIDE + c * 4], &W2h[off]);
            cp16(&SB_lo[k2 * SB2_STRIDE + c * 4], &W2l[off]);
        }
        cp_wait_all();
        __syncthreads();

#pragma unroll
        for (int kk = 0; kk < 2; kk++) {
            int ko = kk * 8;
            int kb = s * 16 + ko;
            unsigned ah[2][4], al[2][4];
#pragma unroll
            for (int mi = 0; mi < 2; mi++) {
                int mr = wm * 32 + mi * 16;
                ah[mi][0] = Hs_hi[(kb + t)     * HS_STRIDE + mr + g];
                ah[mi][1] = Hs_hi[(kb + t)     * HS_STRIDE + mr + g + 8];
                ah[mi][2] = Hs_hi[(kb + t + 4) * HS_STRIDE + mr + g];
                ah[mi][3] = Hs_hi[(kb + t + 4) * HS_STRIDE + mr + g + 8];
                al[mi][0] = Hs_lo[(kb + t)     * HS_STRIDE + mr + g];
                al[mi][1] = Hs_lo[(kb + t)     * HS_STRIDE + mr + g + 8];
                al[mi][2] = Hs_lo[(kb + t + 4) * HS_STRIDE + mr + g];
                al[mi][3] = Hs_lo[(kb + t + 4) * HS_STRIDE + mr + g + 8];
            }
#pragma unroll
            for (int ni = 0; ni < 4; ni++) {
                int nc = wn * 32 + ni * 8;
                unsigned bh[2], bl[2];
                bh[0] = SB_hi[(ko + t)     * SB2_STRIDE + nc + g];
                bh[1] = SB_hi[(ko + t + 4) * SB2_STRIDE + nc + g];
                bl[0] = SB_lo[(ko + t)     * SB2_STRIDE + nc + g];
                bl[1] = SB_lo[(ko + t + 4) * SB2_STRIDE + nc + g];
#pragma unroll
                for (int mi = 0; mi < 2; mi++) {
                    mma_bf16(acc2[mi][ni], ah[mi], bh);
                    mma_bf16(acc2[mi][ni], ah[mi], bl);
                    mma_bf16(acc2[mi][ni], al[mi], bh);
                }
            }
        }
        __syncthreads();
    }

    // Output epilogue
#pragma unroll
    for (int mi = 0; mi < 2; mi++) {
        int r0 = row0 + wm * 32 + mi * 16 + g;
        int r1 = r0 + 8;
#pragma unroll
        for (int ni = 0; ni < 4; ni++) {
            int c = wn * 32 + ni * 8 + 2 * t;
            float bb0 = __ldg(&b2[c]), bb1 = __ldg(&b2[c + 1]);
            float2 v0 = make_float2(acc2[mi][ni][0] + bb0, acc2[mi][ni][1] + bb1);
            float2 v1 = make_float2(acc2[mi][ni][2] + bb0, acc2[mi][ni][3] + bb1);
            if (r0 < N_DET) *reinterpret_cast<float2*>(&out[(size_t)r0 * OUT_DIM + c]) = v0;
            if (r1 < N_DET) *reinterpret_cast<float2*>(&out[(size_t)r1 * OUT_DIM + c]) = v1;
        }
    }
}

// ---------------------------------------------------------------------------
// Edge phase: 8 lanes per edge (4 edges per warp).
// ---------------------------------------------------------------------------
__global__ void __launch_bounds__(256)
edge_kernel(const void* __restrict__ einds, float* __restrict__ out, int nE)
{
    long long warp = (long long)((blockIdx.x * blockDim.x + threadIdx.x) >> 5);
    int lane = threadIdx.x & 31;
    int sub = lane >> 3;
    int l   = lane & 7;
    long long e = warp * 4 + sub;
    if (e >= nE) return;

    long long i1, i2;
    if (g_idx64) {
        const long long* E = (const long long*)einds;
        i1 = __ldg(&E[3 * e + 1]);
        i2 = __ldg(&E[3 * e + 2]);
    } else {
        const int* E = (const int*)einds;
        i1 = __ldg(&E[3 * e + 1]);
        i2 = __ldg(&E[3 * e + 2]);
    }

    const float4* s = reinterpret_cast<const float4*>(g_S + i1 * OUT_DIM);
    const float4* o = reinterpret_cast<const float4*>(g_O + i2 * OUT_DIM);

    float4 a0 = s[l], a1 = s[l + 8], a2 = s[l + 16], a3 = s[l + 24];
    float4 b0 = o[l], b1 = o[l + 8], b2 = o[l + 16], b3 = o[l + 24];

    float sum = a0.x * b0.x + a0.y * b0.y + a0.z * b0.z + a0.w * b0.w
              + a1.x * b1.x + a1.y * b1.y + a1.z * b1.z + a1.w * b1.w
              + a2.x * b2.x + a2.y * b2.y + a2.z * b2.z + a2.w * b2.w
              + a3.x * b3.x + a3.y * b3.y + a3.z * b3.z + a3.w * b3.w;

    sum += __shfl_xor_sync(0xffffffffu, sum, 4);
    sum += __shfl_xor_sync(0xffffffffu, sum, 2);
    sum += __shfl_xor_sync(0xffffffffu, sum, 1);

    if (l == 0)
        out[e] = 1.f / (1.f + __expf(-sum));
}

extern "C" void kernel_launch(void* const* d_in, const int* in_sizes, int n_in,
                              void* d_out, int out_size)
{
    const float* X     = (const float*)d_in[0];
    const void*  E     = d_in[1];
    const float* Ws_w1 = (const float*)d_in[2];
    const float* Ws_b1 = (const float*)d_in[3];
    const float* Ws_w2 = (const float*)d_in[4];
    const float* Ws_b2 = (const float*)d_in[5];
    const float* Wo_w1 = (const float*)d_in[6];
    const float* Wo_b1 = (const float*)d_in[7];
    const float* Wo_w2 = (const float*)d_in[8];
    const float* Wo_b2 = (const float*)d_in[9];

    cudaFuncSetAttribute(fused_mlp, cudaFuncAttributeMaxDynamicSharedMemorySize,
                         SMEM_WORDS * 4);

    probe_dtype<<<1, 1>>>((const long long*)E);

    int nx = N_DET * IN_P;
    prep_X<<<(nx + 255) / 256, 256>>>(X);
    int nw = 2 * IN_P * HID_DIM + 2 * HID_P * OUT_DIM;
    prep_W<<<(nw + 255) / 256, 256>>>(Ws_w1, Wo_w1, Ws_w2, Wo_w2);

    dim3 gf((N_DET + 63) / 64, 2);               // (313, 2)
    fused_mlp<<<gf, 256, SMEM_WORDS * 4>>>(Ws_b1, Wo_b1, Ws_b2, Wo_b2);

    int nE = in_sizes[1] / 3;                    // 1,000,000
    long long totalWarps = ((long long)nE + 3) / 4;
    long long totalThreads = totalWarps * 32;
    int nThreads = 256;
    int nBlocks = (int)((totalThreads + nThreads - 1) / nThreads);
    edge_kernel<<<nBlocks, nThreads>>>(E, (float*)d_out, nE);
}

// round 11
// speedup vs baseline: 1.0548x; 1.0548x over previous
#include <cuda_runtime.h>
#include <cuda_bf16.h>

// Problem constants
#define N_DET   20000
#define IN_DIM  151
#define HID_DIM 256
#define OUT_DIM 128
#define IN_P    80       // padded k-pairs for IN_DIM (76 real, 4 zero) -> 5 stages of 16
#define HID_P   128      // k-pairs for HID_DIM -> 8 stages of 16

// Scratch (allocation forbidden -> __device__ globals)
__device__ __align__(16) float    g_S[N_DET * OUT_DIM];
__device__ __align__(16) float    g_O[N_DET * OUT_DIM];
__device__ __align__(16) unsigned g_Xp_hi[N_DET * IN_P];
__device__ __align__(16) unsigned g_Xp_lo[N_DET * IN_P];
__device__ __align__(16) unsigned g_Hp_hi[2][N_DET * HID_P];  // packed H pairs per net
__device__ __align__(16) unsigned g_Hp_lo[2][N_DET * HID_P];
__device__ __align__(16) unsigned g_W1p_hi[2][IN_P * HID_DIM];
__device__ __align__(16) unsigned g_W1p_lo[2][IN_P * HID_DIM];
__device__ __align__(16) unsigned g_W2p_hi[2][HID_P * OUT_DIM];
__device__ __align__(16) unsigned g_W2p_lo[2][HID_P * OUT_DIM];
__device__ int g_idx64;

// ---------------------------------------------------------------------------
__global__ void probe_dtype(const long long* __restrict__ e)
{
    bool ok64 = true;
    for (int i = 0; i < 48; i++) {
        long long v = e[i];
        if (v < 0 || v >= N_DET) ok64 = false;
    }
    g_idx64 = ok64 ? 1 : 0;
}

// ---------------------------------------------------------------------------
// bf16 split helpers
// ---------------------------------------------------------------------------
__device__ __forceinline__ void split_bf16(float v, unsigned short& hi, unsigned short& lo)
{
    __nv_bfloat16 h = __float2bfloat16(v);
    __nv_bfloat16 l = __float2bfloat16(v - __bfloat162float(h));
    hi = __bfloat16_as_ushort(h);
    lo = __bfloat16_as_ushort(l);
}
__device__ __forceinline__ unsigned pack2(unsigned short a, unsigned short b)
{
    return (unsigned)a | ((unsigned)b << 16);
}
__device__ __forceinline__ void split_pair(float v0, float v1, unsigned& hi, unsigned& lo)
{
    unsigned short h0, l0, h1, l1;
    split_bf16(v0, h0, l0);
    split_bf16(v1, h1, l1);
    hi = pack2(h0, h1);
    lo = pack2(l0, l1);
}

// D += A(16x16,row) * B(16x8,col); bf16 inputs, fp32 accum.
__device__ __forceinline__ void mma_bf16(float* d, const unsigned* a, const unsigned* b)
{
    asm("mma.sync.aligned.m16n8k16.row.col.f32.bf16.bf16.f32 "
        "{%0,%1,%2,%3}, {%4,%5,%6,%7}, {%8,%9}, {%0,%1,%2,%3};"
        : "+f"(d[0]), "+f"(d[1]), "+f"(d[2]), "+f"(d[3])
        : "r"(a[0]), "r"(a[1]), "r"(a[2]), "r"(a[3]), "r"(b[0]), "r"(b[1]));
}

// cp.async 16B global->shared
__device__ __forceinline__ void cp16(unsigned* dst, const unsigned* src)
{
    unsigned d = (unsigned)__cvta_generic_to_shared(dst);
    asm volatile("cp.async.cg.shared.global [%0], [%1], 16;" :: "r"(d), "l"(src));
}

// ---------------------------------------------------------------------------
// Prep: split X into packed bf16 k-pairs.
// ---------------------------------------------------------------------------
__global__ void prep_X(const float* __restrict__ X)
{
    int idx = blockIdx.x * blockDim.x + threadIdx.x;
    if (idx >= N_DET * IN_P) return;
    int row = idx / IN_P, j = idx - row * IN_P;
    float v0 = (2 * j     < IN_DIM) ? X[(size_t)row * IN_DIM + 2 * j]     : 0.f;
    float v1 = (2 * j + 1 < IN_DIM) ? X[(size_t)row * IN_DIM + 2 * j + 1] : 0.f;
    unsigned hi, lo;
    split_pair(v0, v1, hi, lo);
    g_Xp_hi[idx] = hi;
    g_Xp_lo[idx] = lo;
}

// Prep: split both nets' W1 and W2.
__global__ void prep_W(const float* __restrict__ Ws_w1, const float* __restrict__ Wo_w1,
                       const float* __restrict__ Ws_w2, const float* __restrict__ Wo_w2)
{
    int idx = blockIdx.x * blockDim.x + threadIdx.x;
    const int W1TOT = 2 * IN_P * HID_DIM;
    const int W2TOT = 2 * HID_P * OUT_DIM;
    if (idx < W1TOT) {
        int net = idx / (IN_P * HID_DIM);
        int r = idx - net * (IN_P * HID_DIM);
        int j = r / HID_DIM, n = r - j * HID_DIM;
        const float* W = net ? Wo_w1 : Ws_w1;
        float v0 = (2 * j     < IN_DIM) ? W[(size_t)(2 * j)     * HID_DIM + n] : 0.f;
        float v1 = (2 * j + 1 < IN_DIM) ? W[(size_t)(2 * j + 1) * HID_DIM + n] : 0.f;
        unsigned hi, lo;
        split_pair(v0, v1, hi, lo);
        g_W1p_hi[net][r] = hi;
        g_W1p_lo[net][r] = lo;
    } else if (idx < W1TOT + W2TOT) {
        int k = idx - W1TOT;
        int net = k / (HID_P * OUT_DIM);
        int r = k - net * (HID_P * OUT_DIM);
        int j = r / OUT_DIM, n = r - j * OUT_DIM;
        const float* W = net ? Wo_w2 : Ws_w2;
        float v0 = W[(size_t)(2 * j)     * OUT_DIM + n];
        float v1 = W[(size_t)(2 * j + 1) * OUT_DIM + n];
        unsigned hi, lo;
        split_pair(v0, v1, hi, lo);
        g_W2p_hi[net][r] = hi;
        g_W2p_lo[net][r] = lo;
    }
}

// ---------------------------------------------------------------------------
// Shared smem geometry for both GEMMs: CTA tile 128x64, BK = 16 pairs,
// double-buffered. SA [2][128][20], SB [2][16][72]. 59.4 KB -> 3 CTAs/SM.
// 8 warps as 4(m) x 2(n); warp tile 32x32; acc[2][4][4] = 32 regs.
// ---------------------------------------------------------------------------
#define SA_BUF 2560                  // 128*20 words per half per buffer
#define SB_BUF 1152                  // 16*72
#define G_SMEM_WORDS (2 * SA_BUF * 2 + 2 * SB_BUF * 2)   // 14848 words = 59392 B

// Compute one 16-pair stage from buffers. Shared by both kernels.
#define GEMM_COMPUTE(sa_h, sa_l, sb_h, sb_l, NI)                                   \
    _Pragma("unroll")                                                              \
    for (int kk = 0; kk < 2; kk++) {                                               \
        int ko = kk * 8;                                                           \
        unsigned ah[2][4], al[2][4];                                               \
        _Pragma("unroll")                                                          \
        for (int mi = 0; mi < 2; mi++) {                                           \
            int mr = wm * 32 + mi * 16;                                            \
            ah[mi][0] = sa_h[(mr + g)     * 20 + ko + t];                          \
            ah[mi][1] = sa_h[(mr + g + 8) * 20 + ko + t];                          \
            ah[mi][2] = sa_h[(mr + g)     * 20 + ko + t + 4];                      \
            ah[mi][3] = sa_h[(mr + g + 8) * 20 + ko + t + 4];                      \
            al[mi][0] = sa_l[(mr + g)     * 20 + ko + t];                          \
            al[mi][1] = sa_l[(mr + g + 8) * 20 + ko + t];                          \
            al[mi][2] = sa_l[(mr + g)     * 20 + ko + t + 4];                      \
            al[mi][3] = sa_l[(mr + g + 8) * 20 + ko + t + 4];                      \
        }                                                                          \
        _Pragma("unroll")                                                          \
        for (int ni = 0; ni < NI; ni++) {                                          \
            int nc = wn * 32 + ni * 8;                                             \
            unsigned bh[2], bl[2];                                                 \
            bh[0] = sb_h[(ko + t)     * 72 + nc + g];                              \
            bh[1] = sb_h[(ko + t + 4) * 72 + nc + g];                              \
            bl[0] = sb_l[(ko + t)     * 72 + nc + g];                              \
            bl[1] = sb_l[(ko + t + 4) * 72 + nc + g];                              \
            _Pragma("unroll")                                                      \
            for (int mi = 0; mi < 2; mi++) {                                       \
                mma_bf16(acc[mi][ni], ah[mi], bh);                                 \
                mma_bf16(acc[mi][ni], ah[mi], bl);                                 \
                mma_bf16(acc[mi][ni], al[mi], bh);                                 \
            }                                                                      \
        }                                                                          \
    }

// ---------------------------------------------------------------------------
// gemm1: H = relu(X @ W1 + b1), writes split-packed pairs to g_Hp.
// grid (4 ntiles, 157 mtiles, 2 nets)
// ---------------------------------------------------------------------------
__global__ __launch_bounds__(256, 3)
void gemm1(const float* __restrict__ b1s, const float* __restrict__ b1o)
{
    extern __shared__ unsigned sm[];
    unsigned* SA_hi = sm;
    unsigned* SA_lo = SA_hi + 2 * SA_BUF;
    unsigned* SB_hi = SA_lo + 2 * SA_BUF;
    unsigned* SB_lo = SB_hi + 2 * SB_BUF;

    const int tid = threadIdx.x, warp = tid >> 5, lane = tid & 31;
    const int g = lane >> 2, t = lane & 3;
    const int wm = warp >> 1, wn = warp & 1;
    const int n0 = blockIdx.x * 64;
    const int row0 = blockIdx.y * 128;
    const int net = blockIdx.z;

    const unsigned* __restrict__ Wh = g_W1p_hi[net];
    const unsigned* __restrict__ Wl = g_W1p_lo[net];
    const float* __restrict__ b1 = net ? b1o : b1s;
    unsigned* __restrict__ Hh = g_Hp_hi[net];
    unsigned* __restrict__ Hl = g_Hp_lo[net];

    // per-thread load coordinates
    const int lrow = tid >> 2, lcol = (tid & 3) * 4;
    int ga0 = row0 + lrow;      if (ga0 >= N_DET) ga0 = N_DET - 1;
    int ga1 = row0 + lrow + 64; if (ga1 >= N_DET) ga1 = N_DET - 1;
    const int bk2 = tid >> 4, bcol = (tid & 15) * 4;

#define LOAD1(s, buf) do {                                                        \
        size_t o0 = (size_t)ga0 * IN_P + (s) * 16 + lcol;                         \
        size_t o1 = (size_t)ga1 * IN_P + (s) * 16 + lcol;                         \
        unsigned* dh = SA_hi + (buf) * SA_BUF;                                    \
        unsigned* dl = SA_lo + (buf) * SA_BUF;                                    \
        cp16(&dh[lrow * 20 + lcol], &g_Xp_hi[o0]);                                \
        cp16(&dh[(lrow + 64) * 20 + lcol], &g_Xp_hi[o1]);                         \
        cp16(&dl[lrow * 20 + lcol], &g_Xp_lo[o0]);                                \
        cp16(&dl[(lrow + 64) * 20 + lcol], &g_Xp_lo[o1]);                         \
        size_t ob = (size_t)((s) * 16 + bk2) * HID_DIM + n0 + bcol;               \
        cp16(&SB_hi[(buf) * SB_BUF + bk2 * 72 + bcol], &Wh[ob]);                  \
        cp16(&SB_lo[(buf) * SB_BUF + bk2 * 72 + bcol], &Wl[ob]);                  \
        asm volatile("cp.async.commit_group;" ::: "memory");                      \
    } while (0)

    float acc[2][4][4];
#pragma unroll
    for (int mi = 0; mi < 2; mi++)
#pragma unroll
        for (int ni = 0; ni < 4; ni++)
#pragma unroll
            for (int r = 0; r < 4; r++) acc[mi][ni][r] = 0.f;

    LOAD1(0, 0);
    for (int s = 0; s < 5; s++) {
        if (s < 4) {
            LOAD1(s + 1, (s + 1) & 1);
            asm volatile("cp.async.wait_group 1;" ::: "memory");
        } else {
            asm volatile("cp.async.wait_group 0;" ::: "memory");
        }
        __syncthreads();
        const unsigned* sa_h = SA_hi + (s & 1) * SA_BUF;
        const unsigned* sa_l = SA_lo + (s & 1) * SA_BUF;
        const unsigned* sb_h = SB_hi + (s & 1) * SB_BUF;
        const unsigned* sb_l = SB_lo + (s & 1) * SB_BUF;
        GEMM_COMPUTE(sa_h, sa_l, sb_h, sb_l, 4)
        __syncthreads();
    }
#undef LOAD1

    // Epilogue: bias + relu, split-pack, write H pairs
#pragma unroll
    for (int mi = 0; mi < 2; mi++) {
        int r0 = row0 + wm * 32 + mi * 16 + g;
        int r1 = r0 + 8;
#pragma unroll
        for (int ni = 0; ni < 4; ni++) {
            int c0 = n0 + wn * 32 + ni * 8 + 2 * t;
            float bb0 = __ldg(&b1[c0]), bb1 = __ldg(&b1[c0 + 1]);
            float v00 = fmaxf(acc[mi][ni][0] + bb0, 0.f);
            float v01 = fmaxf(acc[mi][ni][1] + bb1, 0.f);
            float v10 = fmaxf(acc[mi][ni][2] + bb0, 0.f);
            float v11 = fmaxf(acc[mi][ni][3] + bb1, 0.f);
            int k2 = c0 >> 1;
            unsigned hi, lo;
            if (r0 < N_DET) {
                split_pair(v00, v01, hi, lo);
                Hh[(size_t)r0 * HID_P + k2] = hi;
                Hl[(size_t)r0 * HID_P + k2] = lo;
            }
            if (r1 < N_DET) {
                split_pair(v10, v11, hi, lo);
                Hh[(size_t)r1 * HID_P + k2] = hi;
                Hl[(size_t)r1 * HID_P + k2] = lo;
            }
        }
    }
}

// ---------------------------------------------------------------------------
// gemm2: T = H @ W2 + b2 -> g_S / g_O.  grid (2 ntiles, 157 mtiles, 2 nets)
// ---------------------------------------------------------------------------
__global__ __launch_bounds__(256, 3)
void gemm2(const float* __restrict__ b2s, const float* __restrict__ b2o)
{
    extern __shared__ unsigned sm[];
    unsigned* SA_hi = sm;
    unsigned* SA_lo = SA_hi + 2 * SA_BUF;
    unsigned* SB_hi = SA_lo + 2 * SA_BUF;
    unsigned* SB_lo = SB_hi + 2 * SB_BUF;

    const int tid = threadIdx.x, warp = tid >> 5, lane = tid & 31;
    const int g = lane >> 2, t = lane & 3;
    const int wm = warp >> 1, wn = warp & 1;
    const int n0 = blockIdx.x * 64;
    const int row0 = blockIdx.y * 128;
    const int net = blockIdx.z;

    const unsigned* __restrict__ Ah = g_Hp_hi[net];
    const unsigned* __restrict__ Al = g_Hp_lo[net];
    const unsigned* __restrict__ Wh = g_W2p_hi[net];
    const unsigned* __restrict__ Wl = g_W2p_lo[net];
    const float* __restrict__ b2 = net ? b2o : b2s;
    float* __restrict__ out = net ? g_O : g_S;

    const int lrow = tid >> 2, lcol = (tid & 3) * 4;
    int ga0 = row0 + lrow;      if (ga0 >= N_DET) ga0 = N_DET - 1;
    int ga1 = row0 + lrow + 64; if (ga1 >= N_DET) ga1 = N_DET - 1;
    const int bk2 = tid >> 4, bcol = (tid & 15) * 4;

#define LOAD2(s, buf) do {                                                        \
        size_t o0 = (size_t)ga0 * HID_P + (s) * 16 + lcol;                        \
        size_t o1 = (size_t)ga1 * HID_P + (s) * 16 + lcol;                        \
        unsigned* dh = SA_hi + (buf) * SA_BUF;                                    \
        unsigned* dl = SA_lo + (buf) * SA_BUF;                                    \
        cp16(&dh[lrow * 20 + lcol], &Ah[o0]);                                     \
        cp16(&dh[(lrow + 64) * 20 + lcol], &Ah[o1]);                              \
        cp16(&dl[lrow * 20 + lcol], &Al[o0]);                                     \
        cp16(&dl[(lrow + 64) * 20 + lcol], &Al[o1]);                              \
        size_t ob = (size_t)((s) * 16 + bk2) * OUT_DIM + n0 + bcol;               \
        cp16(&SB_hi[(buf) * SB_BUF + bk2 * 72 + bcol], &Wh[ob]);                  \
        cp16(&SB_lo[(buf) * SB_BUF + bk2 * 72 + bcol], &Wl[ob]);                  \
        asm volatile("cp.async.commit_group;" ::: "memory");                      \
    } while (0)

    float acc[2][4][4];
#pragma unroll
    for (int mi = 0; mi < 2; mi++)
#pragma unroll
        for (int ni = 0; ni < 4; ni++)
#pragma unroll
            for (int r = 0; r < 4; r++) acc[mi][ni][r] = 0.f;

    LOAD2(0, 0);
    for (int s = 0; s < 8; s++) {
        if (s < 7) {
            LOAD2(s + 1, (s + 1) & 1);
            asm volatile("cp.async.wait_group 1;" ::: "memory");
        } else {
            asm volatile("cp.async.wait_group 0;" ::: "memory");
        }
        __syncthreads();
        const unsigned* sa_h = SA_hi + (s & 1) * SA_BUF;
        const unsigned* sa_l = SA_lo + (s & 1) * SA_BUF;
        const unsigned* sb_h = SB_hi + (s & 1) * SB_BUF;
        const unsigned* sb_l = SB_lo + (s & 1) * SB_BUF;
        GEMM_COMPUTE(sa_h, sa_l, sb_h, sb_l, 4)
        __syncthreads();
    }
#undef LOAD2

    // Output epilogue
#pragma unroll
    for (int mi = 0; mi < 2; mi++) {
        int r0 = row0 + wm * 32 + mi * 16 + g;
        int r1 = r0 + 8;
#pragma unroll
        for (int ni = 0; ni < 4; ni++) {
            int c = n0 + wn * 32 + ni * 8 + 2 * t;
            float bb0 = __ldg(&b2[c]), bb1 = __ldg(&b2[c + 1]);
            float2 v0 = make_float2(acc[mi][ni][0] + bb0, acc[mi][ni][1] + bb1);
            float2 v1 = make_float2(acc[mi][ni][2] + bb0, acc[mi][ni][3] + bb1);
            if (r0 < N_DET) *reinterpret_cast<float2*>(&out[(size_t)r0 * OUT_DIM + c]) = v0;
            if (r1 < N_DET) *reinterpret_cast<float2*>(&out[(size_t)r1 * OUT_DIM + c]) = v1;
        }
    }
}

// ---------------------------------------------------------------------------
// Edge phase: 8 lanes per edge (4 edges per warp).
// ---------------------------------------------------------------------------
__global__ void __launch_bounds__(256)
edge_kernel(const void* __restrict__ einds, float* __restrict__ out, int nE)
{
    long long warp = (long long)((blockIdx.x * blockDim.x + threadIdx.x) >> 5);
    int lane = threadIdx.x & 31;
    int sub = lane >> 3;
    int l   = lane & 7;
    long long e = warp * 4 + sub;
    if (e >= nE) return;

    long long i1, i2;
    if (g_idx64) {
        const long long* E = (const long long*)einds;
        i1 = __ldg(&E[3 * e + 1]);
        i2 = __ldg(&E[3 * e + 2]);
    } else {
        const int* E = (const int*)einds;
        i1 = __ldg(&E[3 * e + 1]);
        i2 = __ldg(&E[3 * e + 2]);
    }

    const float4* s = reinterpret_cast<const float4*>(g_S + i1 * OUT_DIM);
    const float4* o = reinterpret_cast<const float4*>(g_O + i2 * OUT_DIM);

    float4 a0 = s[l], a1 = s[l + 8], a2 = s[l + 16], a3 = s[l + 24];
    float4 b0 = o[l], b1 = o[l + 8], b2 = o[l + 16], b3 = o[l + 24];

    float sum = a0.x * b0.x + a0.y * b0.y + a0.z * b0.z + a0.w * b0.w
              + a1.x * b1.x + a1.y * b1.y + a1.z * b1.z + a1.w * b1.w
              + a2.x * b2.x + a2.y * b2.y + a2.z * b2.z + a2.w * b2.w
              + a3.x * b3.x + a3.y * b3.y + a3.z * b3.z + a3.w * b3.w;

    sum += __shfl_xor_sync(0xffffffffu, sum, 4);
    sum += __shfl_xor_sync(0xffffffffu, sum, 2);
    sum += __shfl_xor_sync(0xffffffffu, sum, 1);

    if (l == 0)
        out[e] = 1.f / (1.f + __expf(-sum));
}

extern "C" void kernel_launch(void* const* d_in, const int* in_sizes, int n_in,
                              void* d_out, int out_size)
{
    const float* X     = (const float*)d_in[0];
    const void*  E     = d_in[1];
    const float* Ws_w1 = (const float*)d_in[2];
    const float* Ws_b1 = (const float*)d_in[3];
    const float* Ws_w2 = (const float*)d_in[4];
    const float* Ws_b2 = (const float*)d_in[5];
    const float* Wo_w1 = (const float*)d_in[6];
    const float* Wo_b1 = (const float*)d_in[7];
    const float* Wo_w2 = (const float*)d_in[8];
    const float* Wo_b2 = (const float*)d_in[9];

    cudaFuncSetAttribute(gemm1, cudaFuncAttributeMaxDynamicSharedMemorySize,
                         G_SMEM_WORDS * 4);
    cudaFuncSetAttribute(gemm2, cudaFuncAttributeMaxDynamicSharedMemorySize,
                         G_SMEM_WORDS * 4);

    probe_dtype<<<1, 1>>>((const long long*)E);

    int nx = N_DET * IN_P;
    prep_X<<<(nx + 255) / 256, 256>>>(X);
    int nw = 2 * IN_P * HID_DIM + 2 * HID_P * OUT_DIM;
    prep_W<<<(nw + 255) / 256, 256>>>(Ws_w1, Wo_w1, Ws_w2, Wo_w2);

    dim3 g1(HID_DIM / 64, (N_DET + 127) / 128, 2);   // (4, 157, 2)
    gemm1<<<g1, 256, G_SMEM_WORDS * 4>>>(Ws_b1, Wo_b1);

    dim3 g2(OUT_DIM / 64, (N_DET + 127) / 128, 2);   // (2, 157, 2)
    gemm2<<<g2, 256, G_SMEM_WORDS * 4>>>(Ws_b2, Wo_b2);

    int nE = in_sizes[1] / 3;                        // 1,000,000
    long long totalWarps = ((long long)nE + 3) / 4;
    long long totalThreads = totalWarps * 32;
    int nThreads = 256;
    int nBlocks = (int)((totalThreads + nThreads - 1) / nThreads);
    edge_kernel<<<nBlocks, nThreads>>>(E, (float*)d_out, nE);
}

// round 12
// speedup vs baseline: 1.1002x; 1.0431x over previous
#include <cuda_runtime.h>
#include <cuda_bf16.h>

// Problem constants
#define N_DET   20000
#define IN_DIM  151
#define HID_DIM 256
#define OUT_DIM 128
#define IN_P    80       // k-pairs for IN_DIM (76 real, 4 zero) -> 5 stages of 16
#define HID_P   128      // k-pairs for HID_DIM -> 8 stages of 16
#define IN_E    160      // padded elements

typedef unsigned short ushort_t;

// Scratch (allocation forbidden -> __device__ globals)
__device__ __align__(16) float    g_S[N_DET * OUT_DIM];
__device__ __align__(16) float    g_O[N_DET * OUT_DIM];
__device__ __align__(16) unsigned g_Xp_hi[N_DET * IN_P];       // pair-packed rows
__device__ __align__(16) unsigned g_Xp_lo[N_DET * IN_P];
__device__ __align__(16) unsigned g_Hp_hi[2][N_DET * HID_P];   // pair-packed H
__device__ __align__(16) unsigned g_Hp_lo[2][N_DET * HID_P];
__device__ __align__(16) ushort_t g_W1e_hi[2][IN_E * HID_DIM]; // element [k][n]
__device__ __align__(16) ushort_t g_W1e_lo[2][IN_E * HID_DIM];
__device__ __align__(16) ushort_t g_W2e_hi[2][HID_DIM * OUT_DIM];
__device__ __align__(16) ushort_t g_W2e_lo[2][HID_DIM * OUT_DIM];
__device__ int g_idx64;

// ---------------------------------------------------------------------------
__global__ void probe_dtype(const long long* __restrict__ e)
{
    bool ok64 = true;
    for (int i = 0; i < 48; i++) {
        long long v = e[i];
        if (v < 0 || v >= N_DET) ok64 = false;
    }
    g_idx64 = ok64 ? 1 : 0;
}

// ---------------------------------------------------------------------------
// bf16 helpers
// ---------------------------------------------------------------------------
__device__ __forceinline__ void split_bf16(float v, ushort_t& hi, ushort_t& lo)
{
    __nv_bfloat16 h = __float2bfloat16(v);
    __nv_bfloat16 l = __float2bfloat16(v - __bfloat162float(h));
    hi = __bfloat16_as_ushort(h);
    lo = __bfloat16_as_ushort(l);
}
__device__ __forceinline__ unsigned pack2(ushort_t a, ushort_t b)
{
    return (unsigned)a | ((unsigned)b << 16);
}
__device__ __forceinline__ void split_pair(float v0, float v1, unsigned& hi, unsigned& lo)
{
    ushort_t h0, l0, h1, l1;
    split_bf16(v0, h0, l0);
    split_bf16(v1, h1, l1);
    hi = pack2(h0, h1);
    lo = pack2(l0, l1);
}

__device__ __forceinline__ void mma_bf16(float* d, const unsigned* a, const unsigned* b)
{
    asm("mma.sync.aligned.m16n8k16.row.col.f32.bf16.bf16.f32 "
        "{%0,%1,%2,%3}, {%4,%5,%6,%7}, {%8,%9}, {%0,%1,%2,%3};"
        : "+f"(d[0]), "+f"(d[1]), "+f"(d[2]), "+f"(d[3])
        : "r"(a[0]), "r"(a[1]), "r"(a[2]), "r"(a[3]), "r"(b[0]), "r"(b[1]));
}

__device__ __forceinline__ void ldsm_x4(unsigned* r, const void* p)
{
    unsigned a = (unsigned)__cvta_generic_to_shared(p);
    asm volatile("ldmatrix.sync.aligned.m8n8.x4.shared.b16 {%0,%1,%2,%3}, [%4];"
                 : "=r"(r[0]), "=r"(r[1]), "=r"(r[2]), "=r"(r[3]) : "r"(a));
}
__device__ __forceinline__ void ldsm_x4_t(unsigned* r, const void* p)
{
    unsigned a = (unsigned)__cvta_generic_to_shared(p);
    asm volatile("ldmatrix.sync.aligned.m8n8.x4.trans.shared.b16 {%0,%1,%2,%3}, [%4];"
                 : "=r"(r[0]), "=r"(r[1]), "=r"(r[2]), "=r"(r[3]) : "r"(a));
}

// cp.async 16B global->shared
__device__ __forceinline__ void cp16(const void* dst, const void* src)
{
    unsigned d = (unsigned)__cvta_generic_to_shared(dst);
    asm volatile("cp.async.cg.shared.global [%0], [%1], 16;" :: "r"(d), "l"(src));
}

// ---------------------------------------------------------------------------
// Prep: split X into pair-packed rows.
// ---------------------------------------------------------------------------
__global__ void prep_X(const float* __restrict__ X)
{
    int idx = blockIdx.x * blockDim.x + threadIdx.x;
    if (idx >= N_DET * IN_P) return;
    int row = idx / IN_P, j = idx - row * IN_P;
    float v0 = (2 * j     < IN_DIM) ? X[(size_t)row * IN_DIM + 2 * j]     : 0.f;
    float v1 = (2 * j + 1 < IN_DIM) ? X[(size_t)row * IN_DIM + 2 * j + 1] : 0.f;
    unsigned hi, lo;
    split_pair(v0, v1, hi, lo);
    g_Xp_hi[idx] = hi;
    g_Xp_lo[idx] = lo;
}

// Prep: split weights into element-major bf16 hi/lo matrices.
__global__ void prep_W(const float* __restrict__ Ws_w1, const float* __restrict__ Wo_w1,
                       const float* __restrict__ Ws_w2, const float* __restrict__ Wo_w2)
{
    int idx = blockIdx.x * blockDim.x + threadIdx.x;
    const int W1TOT = 2 * IN_E * HID_DIM;     // 81920
    const int W2TOT = 2 * HID_DIM * OUT_DIM;  // 65536
    if (idx < W1TOT) {
        int net = idx / (IN_E * HID_DIM);
        int r = idx - net * (IN_E * HID_DIM);
        int k = r / HID_DIM, n = r - k * HID_DIM;
        const float* W = net ? Wo_w1 : Ws_w1;
        float v = (k < IN_DIM) ? W[(size_t)k * HID_DIM + n] : 0.f;
        ushort_t hi, lo;
        split_bf16(v, hi, lo);
        g_W1e_hi[net][r] = hi;
        g_W1e_lo[net][r] = lo;
    } else if (idx < W1TOT + W2TOT) {
        int j = idx - W1TOT;
        int net = j / (HID_DIM * OUT_DIM);
        int r = j - net * (HID_DIM * OUT_DIM);
        float v = (net ? Wo_w2 : Ws_w2)[r];
        ushort_t hi, lo;
        split_bf16(v, hi, lo);
        g_W2e_hi[net][r] = hi;
        g_W2e_lo[net][r] = lo;
    }
}

// ---------------------------------------------------------------------------
// GEMM geometry: CTA tile 128(m) x 64(n), stage = 32 k-elements (16 pairs),
// double-buffered. SA [2][128][20w] pair-packed; SB [2][32][36w] element rows
// (72 bf16, 64 used). 59392 B smem -> 3 CTAs/SM. 8 warps as 4(m) x 2(n);
// warp tile 32x32. All fragment loads via ldmatrix.
// ---------------------------------------------------------------------------
#define SA_BUF 2560                  // 128*20 words
#define SB_BUF 1152                  // 32*36 words
#define G_SMEM_WORDS (2 * SA_BUF * 2 + 2 * SB_BUF * 2)   // 14848 words = 59392 B

// One stage of compute: 2 k16 chunks, warp tile 32x32, 48 MMAs, 16 LDSM.
#define GEMM_COMPUTE(sa_h, sa_l, sb_h, sb_l)                                       \
    _Pragma("unroll")                                                              \
    for (int kk = 0; kk < 2; kk++) {                                               \
        unsigned ah[2][4], al[2][4];                                               \
        _Pragma("unroll")                                                          \
        for (int mi = 0; mi < 2; mi++) {                                           \
            int mr = wm * 32 + mi * 16 + (lane & 15);                              \
            int kc = kk * 8 + ((lane >> 4) << 2);                                  \
            ldsm_x4(ah[mi], sa_h + mr * 20 + kc);                                  \
            ldsm_x4(al[mi], sa_l + mr * 20 + kc);                                  \
        }                                                                          \
        _Pragma("unroll")                                                          \
        for (int np = 0; np < 2; np++) {                                           \
            unsigned bh[4], bl[4];                                                 \
            int kr = kk * 16 + (lane & 15);                                        \
            int ne = wn * 32 + np * 16 + ((lane >> 4) << 3);                       \
            ldsm_x4_t(bh, (const ushort_t*)sb_h + kr * 72 + ne);                   \
            ldsm_x4_t(bl, (const ushort_t*)sb_l + kr * 72 + ne);                   \
            _Pragma("unroll")                                                      \
            for (int n2 = 0; n2 < 2; n2++) {                                       \
                _Pragma("unroll")                                                  \
                for (int mi = 0; mi < 2; mi++) {                                   \
                    mma_bf16(acc[mi][np * 2 + n2], ah[mi], &bh[n2 * 2]);           \
                    mma_bf16(acc[mi][np * 2 + n2], ah[mi], &bl[n2 * 2]);           \
                    mma_bf16(acc[mi][np * 2 + n2], al[mi], &bh[n2 * 2]);           \
                }                                                                  \
            }                                                                      \
        }                                                                          \
    }

// ---------------------------------------------------------------------------
// gemm1: H = relu(X @ W1 + b1) -> pair-packed g_Hp. grid (4, 157, 2)
// ---------------------------------------------------------------------------
__global__ __launch_bounds__(256, 3)
void gemm1(const float* __restrict__ b1s, const float* __restrict__ b1o)
{
    extern __shared__ unsigned sm[];
    unsigned* SA_hi = sm;
    unsigned* SA_lo = SA_hi + 2 * SA_BUF;
    unsigned* SB_hi = SA_lo + 2 * SA_BUF;
    unsigned* SB_lo = SB_hi + 2 * SB_BUF;

    const int tid = threadIdx.x, warp = tid >> 5, lane = tid & 31;
    const int g = lane >> 2, t = lane & 3;
    const int wm = warp >> 1, wn = warp & 1;
    const int n0 = blockIdx.x * 64;
    const int row0 = blockIdx.y * 128;
    const int net = blockIdx.z;

    const ushort_t* __restrict__ Wh = g_W1e_hi[net];
    const ushort_t* __restrict__ Wl = g_W1e_lo[net];
    const float* __restrict__ b1 = net ? b1o : b1s;
    unsigned* __restrict__ Hh = g_Hp_hi[net];
    unsigned* __restrict__ Hl = g_Hp_lo[net];

    const int lrow = tid >> 2, lcol = (tid & 3) * 4;
    int ga0 = row0 + lrow;      if (ga0 >= N_DET) ga0 = N_DET - 1;
    int ga1 = row0 + lrow + 64; if (ga1 >= N_DET) ga1 = N_DET - 1;
    const int brow = tid >> 3, bchunk = (tid & 7) * 8;   // SB: row 0..31, 8 elem chunk

#define LOAD1(s, buf) do {                                                        \
        size_t o0 = (size_t)ga0 * IN_P + (s) * 16 + lcol;                         \
        size_t o1 = (size_t)ga1 * IN_P + (s) * 16 + lcol;                         \
        unsigned* dh = SA_hi + (buf) * SA_BUF;                                    \
        unsigned* dl = SA_lo + (buf) * SA_BUF;                                    \
        cp16(&dh[lrow * 20 + lcol], &g_Xp_hi[o0]);                                \
        cp16(&dh[(lrow + 64) * 20 + lcol], &g_Xp_hi[o1]);                         \
        cp16(&dl[lrow * 20 + lcol], &g_Xp_lo[o0]);                                \
        cp16(&dl[(lrow + 64) * 20 + lcol], &g_Xp_lo[o1]);                         \
        size_t ob = (size_t)((s) * 32 + brow) * HID_DIM + n0 + bchunk;            \
        cp16((ushort_t*)(SB_hi + (buf) * SB_BUF) + brow * 72 + bchunk, &Wh[ob]);  \
        cp16((ushort_t*)(SB_lo + (buf) * SB_BUF) + brow * 72 + bchunk, &Wl[ob]);  \
        asm volatile("cp.async.commit_group;" ::: "memory");                      \
    } while (0)

    float acc[2][4][4];
#pragma unroll
    for (int mi = 0; mi < 2; mi++)
#pragma unroll
        for (int ni = 0; ni < 4; ni++)
#pragma unroll
            for (int r = 0; r < 4; r++) acc[mi][ni][r] = 0.f;

    LOAD1(0, 0);
    for (int s = 0; s < 5; s++) {
        if (s < 4) {
            LOAD1(s + 1, (s + 1) & 1);
            asm volatile("cp.async.wait_group 1;" ::: "memory");
        } else {
            asm volatile("cp.async.wait_group 0;" ::: "memory");
        }
        __syncthreads();
        const unsigned* sa_h = SA_hi + (s & 1) * SA_BUF;
        const unsigned* sa_l = SA_lo + (s & 1) * SA_BUF;
        const unsigned* sb_h = SB_hi + (s & 1) * SB_BUF;
        const unsigned* sb_l = SB_lo + (s & 1) * SB_BUF;
        GEMM_COMPUTE(sa_h, sa_l, sb_h, sb_l)
        __syncthreads();
    }
#undef LOAD1

    // Epilogue: bias + relu, split-pack, write H pairs
#pragma unroll
    for (int mi = 0; mi < 2; mi++) {
        int r0 = row0 + wm * 32 + mi * 16 + g;
        int r1 = r0 + 8;
#pragma unroll
        for (int ni = 0; ni < 4; ni++) {
            int c0 = n0 + wn * 32 + ni * 8 + 2 * t;
            float bb0 = __ldg(&b1[c0]), bb1 = __ldg(&b1[c0 + 1]);
            float v00 = fmaxf(acc[mi][ni][0] + bb0, 0.f);
            float v01 = fmaxf(acc[mi][ni][1] + bb1, 0.f);
            float v10 = fmaxf(acc[mi][ni][2] + bb0, 0.f);
            float v11 = fmaxf(acc[mi][ni][3] + bb1, 0.f);
            int k2 = c0 >> 1;
            unsigned hi, lo;
            if (r0 < N_DET) {
                split_pair(v00, v01, hi, lo);
                Hh[(size_t)r0 * HID_P + k2] = hi;
                Hl[(size_t)r0 * HID_P + k2] = lo;
            }
            if (r1 < N_DET) {
                split_pair(v10, v11, hi, lo);
                Hh[(size_t)r1 * HID_P + k2] = hi;
                Hl[(size_t)r1 * HID_P + k2] = lo;
            }
        }
    }
}

// ---------------------------------------------------------------------------
// gemm2: T = H @ W2 + b2 -> g_S / g_O.  grid (2, 157, 2)
// ---------------------------------------------------------------------------
__global__ __launch_bounds__(256, 3)
void gemm2(const float* __restrict__ b2s, const float* __restrict__ b2o)
{
    extern __shared__ unsigned sm[];
    unsigned* SA_hi = sm;
    unsigned* SA_lo = SA_hi + 2 * SA_BUF;
    unsigned* SB_hi = SA_lo + 2 * SA_BUF;
    unsigned* SB_lo = SB_hi + 2 * SB_BUF;

    const int tid = threadIdx.x, warp = tid >> 5, lane = tid & 31;
    const int g = lane >> 2, t = lane & 3;
    const int wm = warp >> 1, wn = warp & 1;
    const int n0 = blockIdx.x * 64;
    const int row0 = blockIdx.y * 128;
    const int net = blockIdx.z;

    const unsigned* __restrict__ Ah = g_Hp_hi[net];
    const unsigned* __restrict__ Al = g_Hp_lo[net];
    const ushort_t* __restrict__ Wh = g_W2e_hi[net];
    const ushort_t* __restrict__ Wl = g_W2e_lo[net];
    const float* __restrict__ b2 = net ? b2o : b2s;
    float* __restrict__ out = net ? g_O : g_S;

    const int lrow = tid >> 2, lcol = (tid & 3) * 4;
    int ga0 = row0 + lrow;      if (ga0 >= N_DET) ga0 = N_DET - 1;
    int ga1 = row0 + lrow + 64; if (ga1 >= N_DET) ga1 = N_DET - 1;
    const int brow = tid >> 3, bchunk = (tid & 7) * 8;

#define LOAD2(s, buf) do {                                                        \
        size_t o0 = (size_t)ga0 * HID_P + (s) * 16 + lcol;                        \
        size_t o1 = (size_t)ga1 * HID_P + (s) * 16 + lcol;                        \
        unsigned* dh = SA_hi + (buf) * SA_BUF;                                    \
        unsigned* dl = SA_lo + (buf) * SA_BUF;                                    \
        cp16(&dh[lrow * 20 + lcol], &Ah[o0]);                                     \
        cp16(&dh[(lrow + 64) * 20 + lcol], &Ah[o1]);                              \
        cp16(&dl[lrow * 20 + lcol], &Al[o0]);                                     \
        cp16(&dl[(lrow + 64) * 20 + lcol], &Al[o1]);                              \
        size_t ob = (size_t)((s) * 32 + brow) * OUT_DIM + n0 + bchunk;            \
        cp16((ushort_t*)(SB_hi + (buf) * SB_BUF) + brow * 72 + bchunk, &Wh[ob]);  \
        cp16((ushort_t*)(SB_lo + (buf) * SB_BUF) + brow * 72 + bchunk, &Wl[ob]);  \
        asm volatile("cp.async.commit_group;" ::: "memory");                      \
    } while (0)

    float acc[2][4][4];
#pragma unroll
    for (int mi = 0; mi < 2; mi++)
#pragma unroll
        for (int ni = 0; ni < 4; ni++)
#pragma unroll
            for (int r = 0; r < 4; r++) acc[mi][ni][r] = 0.f;

    LOAD2(0, 0);
    for (int s = 0; s < 8; s++) {
        if (s < 7) {
            LOAD2(s + 1, (s + 1) & 1);
            asm volatile("cp.async.wait_group 1;" ::: "memory");
        } else {
            asm volatile("cp.async.wait_group 0;" ::: "memory");
        }
        __syncthreads();
        const unsigned* sa_h = SA_hi + (s & 1) * SA_BUF;
        const unsigned* sa_l = SA_lo + (s & 1) * SA_BUF;
        const unsigned* sb_h = SB_hi + (s & 1) * SB_BUF;
        const unsigned* sb_l = SB_lo + (s & 1) * SB_BUF;
        GEMM_COMPUTE(sa_h, sa_l, sb_h, sb_l)
        __syncthreads();
    }
#undef LOAD2

    // Output epilogue
#pragma unroll
    for (int mi = 0; mi < 2; mi++) {
        int r0 = row0 + wm * 32 + mi * 16 + g;
        int r1 = r0 + 8;
#pragma unroll
        for (int ni = 0; ni < 4; ni++) {
            int c = n0 + wn * 32 + ni * 8 + 2 * t;
            float bb0 = __ldg(&b2[c]), bb1 = __ldg(&b2[c + 1]);
            float2 v0 = make_float2(acc[mi][ni][0] + bb0, acc[mi][ni][1] + bb1);
            float2 v1 = make_float2(acc[mi][ni][2] + bb0, acc[mi][ni][3] + bb1);
            if (r0 < N_DET) *reinterpret_cast<float2*>(&out[(size_t)r0 * OUT_DIM + c]) = v0;
            if (r1 < N_DET) *reinterpret_cast<float2*>(&out[(size_t)r1 * OUT_DIM + c]) = v1;
        }
    }
}

// ---------------------------------------------------------------------------
// Edge phase: 8 lanes per edge (4 edges per warp).
// ---------------------------------------------------------------------------
__global__ void __launch_bounds__(256)
edge_kernel(const void* __restrict__ einds, float* __restrict__ out, int nE)
{
    long long warp = (long long)((blockIdx.x * blockDim.x + threadIdx.x) >> 5);
    int lane = threadIdx.x & 31;
    int sub = lane >> 3;
    int l   = lane & 7;
    long long e = warp * 4 + sub;
    if (e >= nE) return;

    long long i1, i2;
    if (g_idx64) {
        const long long* E = (const long long*)einds;
        i1 = __ldg(&E[3 * e + 1]);
        i2 = __ldg(&E[3 * e + 2]);
    } else {
        const int* E = (const int*)einds;
        i1 = __ldg(&E[3 * e + 1]);
        i2 = __ldg(&E[3 * e + 2]);
    }

    const float4* s = reinterpret_cast<const float4*>(g_S + i1 * OUT_DIM);
    const float4* o = reinterpret_cast<const float4*>(g_O + i2 * OUT_DIM);

    float4 a0 = s[l], a1 = s[l + 8], a2 = s[l + 16], a3 = s[l + 24];
    float4 b0 = o[l], b1 = o[l + 8], b2 = o[l + 16], b3 = o[l + 24];

    float sum = a0.x * b0.x + a0.y * b0.y + a0.z * b0.z + a0.w * b0.w
              + a1.x * b1.x + a1.y * b1.y + a1.z * b1.z + a1.w * b1.w
              + a2.x * b2.x + a2.y * b2.y + a2.z * b2.z + a2.w * b2.w
              + a3.x * b3.x + a3.y * b3.y + a3.z * b3.z + a3.w * b3.w;

    sum += __shfl_xor_sync(0xffffffffu, sum, 4);
    sum += __shfl_xor_sync(0xffffffffu, sum, 2);
    sum += __shfl_xor_sync(0xffffffffu, sum, 1);

    if (l == 0)
        out[e] = 1.f / (1.f + __expf(-sum));
}

extern "C" void kernel_launch(void* const* d_in, const int* in_sizes, int n_in,
                              void* d_out, int out_size)
{
    const float* X     = (const float*)d_in[0];
    const void*  E     = d_in[1];
    const float* Ws_w1 = (const float*)d_in[2];
    const float* Ws_b1 = (const float*)d_in[3];
    const float* Ws_w2 = (const float*)d_in[4];
    const float* Ws_b2 = (const float*)d_in[5];
    const float* Wo_w1 = (const float*)d_in[6];
    const float* Wo_b1 = (const float*)d_in[7];
    const float* Wo_w2 = (const float*)d_in[8];
    const float* Wo_b2 = (const float*)d_in[9];

    cudaFuncSetAttribute(gemm1, cudaFuncAttributeMaxDynamicSharedMemorySize,
                         G_SMEM_WORDS * 4);
    cudaFuncSetAttribute(gemm2, cudaFuncAttributeMaxDynamicSharedMemorySize,
                         G_SMEM_WORDS * 4);

    probe_dtype<<<1, 1>>>((const long long*)E);

    int nx = N_DET * IN_P;
    prep_X<<<(nx + 255) / 256, 256>>>(X);
    int nw = 2 * IN_E * HID_DIM + 2 * HID_DIM * OUT_DIM;
    prep_W<<<(nw + 255) / 256, 256>>>(Ws_w1, Wo_w1, Ws_w2, Wo_w2);

    dim3 g1(HID_DIM / 64, (N_DET + 127) / 128, 2);   // (4, 157, 2)
    gemm1<<<g1, 256, G_SMEM_WORDS * 4>>>(Ws_b1, Wo_b1);

    dim3 g2(OUT_DIM / 64, (N_DET + 127) / 128, 2);   // (2, 157, 2)
    gemm2<<<g2, 256, G_SMEM_WORDS * 4>>>(Ws_b2, Wo_b2);

    int nE = in_sizes[1] / 3;                        // 1,000,000
    long long totalWarps = ((long long)nE + 3) / 4;
    long long totalThreads = totalWarps * 32;
    int nThreads = 256;
    int nBlocks = (int)((totalThreads + nThreads - 1) / nThreads);
    edge_kernel<<<nBlocks, nThreads>>>(E, (float*)d_out, nE);
}